// round 6
// baseline (speedup 1.0000x reference)
#include <cuda_runtime.h>
#include <cuda_bf16.h>
#include <math.h>

#define NN 50000
#define NE 640000
#define F  128
#define NG 512

// ---------------- scratch (device globals, no allocation) ----------------
__device__ int   g_ei32flag;            // nonzero => edge_index buffer is int32
__device__ int   g_b32flag;             // nonzero => batch buffer is int32
__device__ int   g_src[NE];
__device__ int   g_dst[NE];
__device__ int   g_batch[NN];
__device__ int   g_degE[NN];
__device__ int   g_cursor[NN];
__device__ int   g_rowoff[NN + 1];
__device__ int   g_col[NE];
__device__ float g_dinv[NN];
__device__ __align__(16) float g_bufA[NN * F];
__device__ __align__(16) float g_bufB[NN * F];
__device__ int   g_gstart[NG + 1];

template <int B> __device__ __forceinline__ float* bufptr() {
    return (B == 0) ? g_bufA : g_bufB;
}

// ---------------- dtype detection + normalization ----------------
__global__ void k_reset() {
    int i = blockIdx.x * blockDim.x + threadIdx.x;
    if (i == 0) { g_ei32flag = 0; g_b32flag = 0; }
    if (i < NN) { g_degE[i] = 0; g_cursor[i] = 0; }
}

// OR the odd 32-bit words. Reads only min-size region (safe for either dtype).
// int64 buffer (values < 2^31): odd words are high halves == 0 -> flag stays 0.
// int32 buffer: odd words are real ids -> flag becomes nonzero.
__global__ void k_detect(const int* __restrict__ ei_raw,
                         const int* __restrict__ batch_raw) {
    int i = blockIdx.x * blockDim.x + threadIdx.x;
    int v = 0;
    // edge_index: first 2*NE ints are safe either way; scan odd indices
    for (int j = 2 * i + 1; j < 2 * NE; j += 2 * 262144) v |= ei_raw[j];
    if (v) atomicOr(&g_ei32flag, 1);
    int bsum = 0;
    for (int j = 2 * i + 1; j < NN; j += 2 * 262144) bsum |= batch_raw[j];
    if (bsum) atomicOr(&g_b32flag, 1);
}

__global__ void k_convert(const void* __restrict__ ei_raw,
                          const void* __restrict__ batch_raw) {
    int i = blockIdx.x * blockDim.x + threadIdx.x;
    if (i < NE) {
        int s, d;
        if (g_ei32flag) {
            const int* p = (const int*)ei_raw;
            s = p[i]; d = p[NE + i];
        } else {
            const long long* p = (const long long*)ei_raw;
            s = (int)p[i]; d = (int)p[NE + i];
        }
        g_src[i] = min(max(s, 0), NN - 1);
        g_dst[i] = min(max(d, 0), NN - 1);
    }
    if (i < NN) {
        int b;
        if (g_b32flag) b = ((const int*)batch_raw)[i];
        else           b = (int)((const long long*)batch_raw)[i];
        g_batch[i] = min(max(b, 0), NG - 1);
    }
}

// ---------------- graph preprocessing ----------------
__global__ void k_count() {
    int e = blockIdx.x * blockDim.x + threadIdx.x;
    if (e < NE) atomicAdd(&g_degE[g_dst[e]], 1);
}

__global__ void k_dinv() {
    int i = blockIdx.x * blockDim.x + threadIdx.x;
    if (i < NN) g_dinv[i] = rsqrtf((float)(g_degE[i] + 1));  // +1 self loop
}

// single-block exclusive scan over g_degE -> g_rowoff (50k elements)
__global__ void k_scan() {
    __shared__ int wsum[32];
    __shared__ int s_carry;
    int t = threadIdx.x, lane = t & 31, w = t >> 5;
    if (t == 0) s_carry = 0;
    __syncthreads();
    for (int base = 0; base < NN; base += 1024) {
        int i = base + t;
        int v = (i < NN) ? g_degE[i] : 0;
        int x = v;
        #pragma unroll
        for (int o = 1; o < 32; o <<= 1) {
            int y = __shfl_up_sync(0xffffffffu, x, o);
            if (lane >= o) x += y;
        }
        if (lane == 31) wsum[w] = x;
        __syncthreads();
        if (w == 0) {
            int s = wsum[lane];
            #pragma unroll
            for (int o = 1; o < 32; o <<= 1) {
                int y = __shfl_up_sync(0xffffffffu, s, o);
                if (lane >= o) s += y;
            }
            wsum[lane] = s;
        }
        __syncthreads();
        int warp_off = (w > 0) ? wsum[w - 1] : 0;
        if (i < NN) g_rowoff[i] = s_carry + warp_off + x - v;
        __syncthreads();
        if (t == 0) s_carry += wsum[31];
        __syncthreads();
    }
    if (t == 0) g_rowoff[NN] = s_carry;
}

__global__ void k_scatter() {
    int e = blockIdx.x * blockDim.x + threadIdx.x;
    if (e < NE) {
        int d = g_dst[e];
        int pos = atomicAdd(&g_cursor[d], 1);
        g_col[g_rowoff[d] + pos] = g_src[e];
    }
}

// ---------------- dense GEMM: C[M,128] = A[M,128] @ W[128,128] ----------------
template <int SRC, int DST>
__global__ __launch_bounds__(256) void k_sgemm(const float* __restrict__ X,
                                               const float* __restrict__ W, int M) {
    const float* A = (SRC < 0) ? X : bufptr<SRC>();
    float* C = bufptr<DST>();
    __shared__ float As[16][128];
    __shared__ float Bs[16][128];
    int row0 = blockIdx.x * 128;
    int tid = threadIdx.x;
    int tr = (tid >> 4) << 3;
    int tc = (tid & 15) << 3;
    float acc[8][8];
    #pragma unroll
    for (int i = 0; i < 8; i++)
        #pragma unroll
        for (int j = 0; j < 8; j++) acc[i][j] = 0.f;

    for (int k0 = 0; k0 < 128; k0 += 16) {
        #pragma unroll
        for (int it = 0; it < 2; it++) {   // A tile 128x16 (transposed into As[k][row])
            int idx = tid + it * 256;
            int r = idx >> 2;
            int c4 = (idx & 3) << 2;
            float4 a = (row0 + r < M)
                ? *(const float4*)(A + (size_t)(row0 + r) * 128 + k0 + c4)
                : make_float4(0.f, 0.f, 0.f, 0.f);
            As[c4 + 0][r] = a.x; As[c4 + 1][r] = a.y;
            As[c4 + 2][r] = a.z; As[c4 + 3][r] = a.w;
        }
        #pragma unroll
        for (int it = 0; it < 2; it++) {   // W tile 16x128
            int idx = tid + it * 256;
            int r = idx >> 5;
            int c4 = (idx & 31) << 2;
            *(float4*)&Bs[r][c4] = *(const float4*)(W + (k0 + r) * 128 + c4);
        }
        __syncthreads();
        #pragma unroll
        for (int k = 0; k < 16; k++) {
            float ra[8], rb[8];
            #pragma unroll
            for (int i = 0; i < 8; i++) ra[i] = As[k][tr + i];
            #pragma unroll
            for (int j = 0; j < 8; j++) rb[j] = Bs[k][tc + j];
            #pragma unroll
            for (int i = 0; i < 8; i++)
                #pragma unroll
                for (int j = 0; j < 8; j++) acc[i][j] = fmaf(ra[i], rb[j], acc[i][j]);
        }
        __syncthreads();
    }
    #pragma unroll
    for (int i = 0; i < 8; i++) {
        int r = row0 + tr + i;
        if (r < M) {
            *(float4*)(C + (size_t)r * 128 + tc) =
                make_float4(acc[i][0], acc[i][1], acc[i][2], acc[i][3]);
            *(float4*)(C + (size_t)r * 128 + tc + 4) =
                make_float4(acc[i][4], acc[i][5], acc[i][6], acc[i][7]);
        }
    }
}

// ---------------- SpMM aggregate + bias + relu (warp per node) ----------------
template <int SRC, int DST>
__global__ void k_spmm(const float* __restrict__ bias) {
    const float* H = bufptr<SRC>();
    float* O = bufptr<DST>();
    int v = (blockIdx.x * blockDim.x + threadIdx.x) >> 5;
    int lane = threadIdx.x & 31;
    if (v >= NN) return;
    float dv = g_dinv[v];
    float4 h = *(const float4*)(H + (size_t)v * 128 + lane * 4);
    float4 acc = make_float4(dv * h.x, dv * h.y, dv * h.z, dv * h.w);  // self loop
    int beg = g_rowoff[v], end = g_rowoff[v + 1];
    for (int j0 = beg; j0 < end; j0 += 32) {
        int jj = j0 + lane;
        int s_l = 0; float d_l = 0.f;
        if (jj < end) { s_l = g_col[jj]; d_l = g_dinv[s_l]; }
        int cnt = min(32, end - j0);
        for (int t = 0; t < cnt; t++) {
            int s    = __shfl_sync(0xffffffffu, s_l, t);
            float ds = __shfl_sync(0xffffffffu, d_l, t);
            float4 hs = *(const float4*)(H + (size_t)s * 128 + lane * 4);
            acc.x = fmaf(ds, hs.x, acc.x);
            acc.y = fmaf(ds, hs.y, acc.y);
            acc.z = fmaf(ds, hs.z, acc.z);
            acc.w = fmaf(ds, hs.w, acc.w);
        }
    }
    float4 b = *(const float4*)(bias + lane * 4);
    float4 o;
    o.x = fmaxf(fmaf(dv, acc.x, b.x), 0.f);
    o.y = fmaxf(fmaf(dv, acc.y, b.y), 0.f);
    o.z = fmaxf(fmaf(dv, acc.z, b.z), 0.f);
    o.w = fmaxf(fmaf(dv, acc.w, b.w), 0.f);
    *(float4*)(O + (size_t)v * 128 + lane * 4) = o;
}

// ---------------- graph segment boundaries (batch is sorted) ----------------
__global__ void k_bounds() {
    int i = blockIdx.x * blockDim.x + threadIdx.x;
    if (i >= NN) return;
    int b = g_batch[i];
    if (i == 0) {
        for (int g = 0; g <= b; g++) g_gstart[g] = 0;
    } else {
        int bp = g_batch[i - 1];
        for (int g = bp + 1; g <= b; g++) g_gstart[g] = i;
    }
    if (i == NN - 1) {
        for (int g = b + 1; g <= NG; g++) g_gstart[g] = NN;
    }
}

// ---------------- mean pool + MLP head (block per graph) ----------------
template <int SRC>
__global__ __launch_bounds__(128) void k_head(
    const float* __restrict__ ax,
    const float* __restrict__ l1W, const float* __restrict__ l1b,
    const float* __restrict__ axW, const float* __restrict__ axb,
    const float* __restrict__ l2W, const float* __restrict__ l2b,
    float* __restrict__ out) {
    const float* H = bufptr<SRC>();
    int g = blockIdx.x, t = threadIdx.x;
    __shared__ float pooled[128];
    __shared__ float axs[64];
    __shared__ float z[192];
    int s = g_gstart[g], e = g_gstart[g + 1];
    float acc = 0.f;
    for (int v = s; v < e; v++) acc += H[(size_t)v * 128 + t];
    pooled[t] = acc / (float)max(e - s, 1);
    if (t < 64) axs[t] = ax[g * 64 + t];
    __syncthreads();
    float go = l1b[t];
    #pragma unroll 8
    for (int k = 0; k < 128; k++) go = fmaf(pooled[k], l1W[k * 128 + t], go);
    z[t] = go;
    if (t < 64) {
        float ao = axb[t];
        #pragma unroll 8
        for (int k = 0; k < 64; k++) ao = fmaf(axs[k], axW[k * 64 + t], ao);
        z[128 + t] = ao;
    }
    __syncthreads();
    if (t < 8) {
        float o = l2b[t];
        #pragma unroll 8
        for (int k = 0; k < 192; k++) o = fmaf(z[k], l2W[k * 8 + t], o);
        out[g * 8 + t] = o;
    }
}

// ---------------- launch ----------------
extern "C" void kernel_launch(void* const* d_in, const int* in_sizes, int n_in,
                              void* d_out, int out_size) {
    const float* x     = (const float*)d_in[0];
    const void*  ei    = d_in[1];
    const void*  batch = d_in[2];
    const float* ax    = (const float*)d_in[3];
    const float* W1    = (const float*)d_in[4];
    const float* b1    = (const float*)d_in[5];
    const float* W2    = (const float*)d_in[6];
    const float* b2    = (const float*)d_in[7];
    const float* l1W   = (const float*)d_in[8];
    const float* l1b   = (const float*)d_in[9];
    const float* axW   = (const float*)d_in[10];
    const float* axb   = (const float*)d_in[11];
    const float* l2W   = (const float*)d_in[12];
    const float* l2b   = (const float*)d_in[13];
    float* out = (float*)d_out;

    const int TB = 256;
    k_reset  <<<(NN + TB - 1) / TB, TB>>>();
    k_detect <<<(262144 + TB - 1) / TB, TB>>>((const int*)ei, (const int*)batch);
    k_convert<<<(NE + TB - 1) / TB, TB>>>(ei, batch);
    k_count  <<<(NE + TB - 1) / TB, TB>>>();
    k_dinv   <<<(NN + TB - 1) / TB, TB>>>();
    k_scan   <<<1, 1024>>>();
    k_scatter<<<(NE + TB - 1) / TB, TB>>>();

    k_sgemm<-1, 0><<<(NN + 127) / 128, 256>>>(x, W1, NN);        // x @ W1 -> bufA
    k_spmm <0, 1> <<<(NN * 32 + TB - 1) / TB, TB>>>(b1);         // aggregate -> bufB
    k_sgemm<1, 0><<<(NN + 127) / 128, 256>>>(nullptr, W2, NN);   // bufB @ W2 -> bufA
    k_spmm <0, 1> <<<(NN * 32 + TB - 1) / TB, TB>>>(b2);         // aggregate -> bufB

    k_bounds<<<(NN + TB - 1) / TB, TB>>>();
    k_head<1><<<NG, 128>>>(ax, l1W, l1b, axW, axb, l2W, l2b, out);
}

// round 7
// speedup vs baseline: 1.0462x; 1.0462x over previous
#include <cuda_runtime.h>
#include <cuda_bf16.h>
#include <math.h>

#define NN 50000
#define NE 640000
#define F  128
#define NG 512

typedef unsigned long long ull;

// ---------------- scratch (device globals, no allocation) ----------------
__device__ int   g_ei32flag;
__device__ int   g_b32flag;
__device__ int   g_src[NE];
__device__ int   g_dst[NE];
__device__ int   g_batch[NN];
__device__ int   g_degE[NN];
__device__ int   g_cursor[NN];
__device__ int   g_rowoff[NN + 1];
__device__ int   g_col[NE];
__device__ float g_nrm[NE];            // dinv[src] per CSR slot
__device__ float g_dinv[NN];
__device__ __align__(16) float g_bufA[NN * F];
__device__ __align__(16) float g_bufB[NN * F];
__device__ int   g_gstart[NG + 1];

template <int B> __device__ __forceinline__ float* bufptr() {
    return (B == 0) ? g_bufA : g_bufB;
}

// packed fp32x2 helpers (Blackwell FFMA2 via PTX)
__device__ __forceinline__ void ffma2(ull& acc, ull a, ull b) {
    asm("fma.rn.f32x2 %0, %1, %2, %0;" : "+l"(acc) : "l"(a), "l"(b));
}
__device__ __forceinline__ ull pack2(float x) {
    ull r;
    asm("mov.b64 %0, {%1, %1};" : "=l"(r) : "r"(__float_as_uint(x)));
    return r;
}

// ---------------- dtype detection + normalization ----------------
__global__ void k_reset() {
    int i = blockIdx.x * blockDim.x + threadIdx.x;
    if (i == 0) { g_ei32flag = 0; g_b32flag = 0; }
    if (i < NN) { g_degE[i] = 0; g_cursor[i] = 0; }
}

__global__ void k_detect(const int* __restrict__ ei_raw,
                         const int* __restrict__ batch_raw) {
    int i = blockIdx.x * blockDim.x + threadIdx.x;
    int v = 0;
    for (int j = 2 * i + 1; j < 2 * NE; j += 2 * 262144) v |= ei_raw[j];
    if (v) atomicOr(&g_ei32flag, 1);
    int bsum = 0;
    for (int j = 2 * i + 1; j < NN; j += 2 * 262144) bsum |= batch_raw[j];
    if (bsum) atomicOr(&g_b32flag, 1);
}

// convert + degree count fused
__global__ void k_convert(const void* __restrict__ ei_raw,
                          const void* __restrict__ batch_raw) {
    int i = blockIdx.x * blockDim.x + threadIdx.x;
    if (i < NE) {
        int s, d;
        if (g_ei32flag) {
            const int* p = (const int*)ei_raw;
            s = p[i]; d = p[NE + i];
        } else {
            const long long* p = (const long long*)ei_raw;
            s = (int)p[i]; d = (int)p[NE + i];
        }
        s = min(max(s, 0), NN - 1);
        d = min(max(d, 0), NN - 1);
        g_src[i] = s;
        g_dst[i] = d;
        atomicAdd(&g_degE[d], 1);
    }
    if (i < NN) {
        int b;
        if (g_b32flag) b = ((const int*)batch_raw)[i];
        else           b = (int)((const long long*)batch_raw)[i];
        g_batch[i] = min(max(b, 0), NG - 1);
    }
}

// single-block exclusive scan over g_degE -> g_rowoff, fused dinv
__global__ void k_scan() {
    __shared__ int wsum[32];
    __shared__ int s_carry;
    int t = threadIdx.x, lane = t & 31, w = t >> 5;
    if (t == 0) s_carry = 0;
    __syncthreads();
    for (int base = 0; base < NN; base += 1024) {
        int i = base + t;
        int v = (i < NN) ? g_degE[i] : 0;
        if (i < NN) g_dinv[i] = rsqrtf((float)(v + 1));   // +1 self loop
        int x = v;
        #pragma unroll
        for (int o = 1; o < 32; o <<= 1) {
            int y = __shfl_up_sync(0xffffffffu, x, o);
            if (lane >= o) x += y;
        }
        if (lane == 31) wsum[w] = x;
        __syncthreads();
        if (w == 0) {
            int s = wsum[lane];
            #pragma unroll
            for (int o = 1; o < 32; o <<= 1) {
                int y = __shfl_up_sync(0xffffffffu, s, o);
                if (lane >= o) s += y;
            }
            wsum[lane] = s;
        }
        __syncthreads();
        int warp_off = (w > 0) ? wsum[w - 1] : 0;
        if (i < NN) g_rowoff[i] = s_carry + warp_off + x - v;
        __syncthreads();
        if (t == 0) s_carry += wsum[31];
        __syncthreads();
    }
    if (t == 0) g_rowoff[NN] = s_carry;
}

// scatter + per-edge norm fused
__global__ void k_scatter() {
    int e = blockIdx.x * blockDim.x + threadIdx.x;
    if (e < NE) {
        int s = g_src[e];
        int d = g_dst[e];
        int pos = atomicAdd(&g_cursor[d], 1);
        int idx = g_rowoff[d] + pos;
        g_col[idx] = s;
        g_nrm[idx] = g_dinv[s];
    }
}

// ---------------- dense GEMM: C[M,128] = A[M,128] @ W[128,128] (f32x2 FFMA2) ----------------
template <int SRC, int DST>
__global__ __launch_bounds__(256) void k_sgemm(const float* __restrict__ X,
                                               const float* __restrict__ W, int M) {
    const float* A = (SRC < 0) ? X : bufptr<SRC>();
    float* C = bufptr<DST>();
    __shared__ float As[16][128];
    __shared__ float Bs[16][128];
    int row0 = blockIdx.x * 128;
    int tid = threadIdx.x;
    int tr = (tid >> 4) << 3;   // 0..120
    int tc = (tid & 15) << 3;   // 0..120  (8-float => 32B aligned, LDS.64-safe)
    ull acc2[8][4];
    #pragma unroll
    for (int i = 0; i < 8; i++)
        #pragma unroll
        for (int j = 0; j < 4; j++) acc2[i][j] = 0ull;

    for (int k0 = 0; k0 < 128; k0 += 16) {
        #pragma unroll
        for (int it = 0; it < 2; it++) {   // A tile 128x16 (transposed into As[k][row])
            int idx = tid + it * 256;
            int r = idx >> 2;
            int c4 = (idx & 3) << 2;
            float4 a = (row0 + r < M)
                ? *(const float4*)(A + (size_t)(row0 + r) * 128 + k0 + c4)
                : make_float4(0.f, 0.f, 0.f, 0.f);
            As[c4 + 0][r] = a.x; As[c4 + 1][r] = a.y;
            As[c4 + 2][r] = a.z; As[c4 + 3][r] = a.w;
        }
        #pragma unroll
        for (int it = 0; it < 2; it++) {   // W tile 16x128
            int idx = tid + it * 256;
            int r = idx >> 5;
            int c4 = (idx & 31) << 2;
            *(float4*)&Bs[r][c4] = *(const float4*)(W + (k0 + r) * 128 + c4);
        }
        __syncthreads();
        #pragma unroll
        for (int k = 0; k < 16; k++) {
            ull ra2[8], rb2[4];
            #pragma unroll
            for (int i = 0; i < 8; i++) ra2[i] = pack2(As[k][tr + i]);
            #pragma unroll
            for (int j = 0; j < 4; j++)
                rb2[j] = *reinterpret_cast<const ull*>(&Bs[k][tc + 2 * j]);
            #pragma unroll
            for (int i = 0; i < 8; i++)
                #pragma unroll
                for (int j = 0; j < 4; j++) ffma2(acc2[i][j], ra2[i], rb2[j]);
        }
        __syncthreads();
    }
    #pragma unroll
    for (int i = 0; i < 8; i++) {
        int r = row0 + tr + i;
        if (r < M) {
            float2 p0 = *reinterpret_cast<float2*>(&acc2[i][0]);
            float2 p1 = *reinterpret_cast<float2*>(&acc2[i][1]);
            float2 p2 = *reinterpret_cast<float2*>(&acc2[i][2]);
            float2 p3 = *reinterpret_cast<float2*>(&acc2[i][3]);
            *(float4*)(C + (size_t)r * 128 + tc)     = make_float4(p0.x, p0.y, p1.x, p1.y);
            *(float4*)(C + (size_t)r * 128 + tc + 4) = make_float4(p2.x, p2.y, p3.x, p3.y);
        }
    }
}

// ---------------- SpMM aggregate + bias + relu (warp per node, no shuffles) ----------------
template <int SRC, int DST>
__global__ void k_spmm(const float* __restrict__ bias) {
    const float* H = bufptr<SRC>();
    float* O = bufptr<DST>();
    int v = (blockIdx.x * blockDim.x + threadIdx.x) >> 5;
    int lane = threadIdx.x & 31;
    if (v >= NN) return;
    float dv = g_dinv[v];
    float4 h = *(const float4*)(H + (size_t)v * 128 + lane * 4);
    float4 acc = make_float4(dv * h.x, dv * h.y, dv * h.z, dv * h.w);  // self loop
    int beg = g_rowoff[v], end = g_rowoff[v + 1];
    int j = beg;
    for (; j + 4 <= end; j += 4) {
        int s0 = g_col[j], s1 = g_col[j + 1], s2 = g_col[j + 2], s3 = g_col[j + 3];
        float d0 = g_nrm[j], d1 = g_nrm[j + 1], d2 = g_nrm[j + 2], d3 = g_nrm[j + 3];
        float4 h0 = *(const float4*)(H + (size_t)s0 * 128 + lane * 4);
        float4 h1 = *(const float4*)(H + (size_t)s1 * 128 + lane * 4);
        float4 h2 = *(const float4*)(H + (size_t)s2 * 128 + lane * 4);
        float4 h3 = *(const float4*)(H + (size_t)s3 * 128 + lane * 4);
        acc.x = fmaf(d0, h0.x, acc.x); acc.y = fmaf(d0, h0.y, acc.y);
        acc.z = fmaf(d0, h0.z, acc.z); acc.w = fmaf(d0, h0.w, acc.w);
        acc.x = fmaf(d1, h1.x, acc.x); acc.y = fmaf(d1, h1.y, acc.y);
        acc.z = fmaf(d1, h1.z, acc.z); acc.w = fmaf(d1, h1.w, acc.w);
        acc.x = fmaf(d2, h2.x, acc.x); acc.y = fmaf(d2, h2.y, acc.y);
        acc.z = fmaf(d2, h2.z, acc.z); acc.w = fmaf(d2, h2.w, acc.w);
        acc.x = fmaf(d3, h3.x, acc.x); acc.y = fmaf(d3, h3.y, acc.y);
        acc.z = fmaf(d3, h3.z, acc.z); acc.w = fmaf(d3, h3.w, acc.w);
    }
    for (; j < end; j++) {
        int s = g_col[j];
        float ds = g_nrm[j];
        float4 hs = *(const float4*)(H + (size_t)s * 128 + lane * 4);
        acc.x = fmaf(ds, hs.x, acc.x); acc.y = fmaf(ds, hs.y, acc.y);
        acc.z = fmaf(ds, hs.z, acc.z); acc.w = fmaf(ds, hs.w, acc.w);
    }
    float4 b = *(const float4*)(bias + lane * 4);
    float4 o;
    o.x = fmaxf(fmaf(dv, acc.x, b.x), 0.f);
    o.y = fmaxf(fmaf(dv, acc.y, b.y), 0.f);
    o.z = fmaxf(fmaf(dv, acc.z, b.z), 0.f);
    o.w = fmaxf(fmaf(dv, acc.w, b.w), 0.f);
    *(float4*)(O + (size_t)v * 128 + lane * 4) = o;
}

// ---------------- graph segment boundaries (batch is sorted) ----------------
__global__ void k_bounds() {
    int i = blockIdx.x * blockDim.x + threadIdx.x;
    if (i >= NN) return;
    int b = g_batch[i];
    if (i == 0) {
        for (int g = 0; g <= b; g++) g_gstart[g] = 0;
    } else {
        int bp = g_batch[i - 1];
        for (int g = bp + 1; g <= b; g++) g_gstart[g] = i;
    }
    if (i == NN - 1) {
        for (int g = b + 1; g <= NG; g++) g_gstart[g] = NN;
    }
}

// ---------------- mean pool + MLP head (block per graph) ----------------
template <int SRC>
__global__ __launch_bounds__(128) void k_head(
    const float* __restrict__ ax,
    const float* __restrict__ l1W, const float* __restrict__ l1b,
    const float* __restrict__ axW, const float* __restrict__ axb,
    const float* __restrict__ l2W, const float* __restrict__ l2b,
    float* __restrict__ out) {
    const float* H = bufptr<SRC>();
    int g = blockIdx.x, t = threadIdx.x;
    __shared__ float pooled[128];
    __shared__ float axs[64];
    __shared__ float z[192];
    int s = g_gstart[g], e = g_gstart[g + 1];
    float acc = 0.f;
    for (int v = s; v < e; v++) acc += H[(size_t)v * 128 + t];
    pooled[t] = acc / (float)max(e - s, 1);
    if (t < 64) axs[t] = ax[g * 64 + t];
    __syncthreads();
    float go = l1b[t];
    #pragma unroll 8
    for (int k = 0; k < 128; k++) go = fmaf(pooled[k], l1W[k * 128 + t], go);
    z[t] = go;
    if (t < 64) {
        float ao = axb[t];
        #pragma unroll 8
        for (int k = 0; k < 64; k++) ao = fmaf(axs[k], axW[k * 64 + t], ao);
        z[128 + t] = ao;
    }
    __syncthreads();
    if (t < 8) {
        float o = l2b[t];
        #pragma unroll 8
        for (int k = 0; k < 192; k++) o = fmaf(z[k], l2W[k * 8 + t], o);
        out[g * 8 + t] = o;
    }
}

// ---------------- launch ----------------
extern "C" void kernel_launch(void* const* d_in, const int* in_sizes, int n_in,
                              void* d_out, int out_size) {
    const float* x     = (const float*)d_in[0];
    const void*  ei    = d_in[1];
    const void*  batch = d_in[2];
    const float* ax    = (const float*)d_in[3];
    const float* W1    = (const float*)d_in[4];
    const float* b1    = (const float*)d_in[5];
    const float* W2    = (const float*)d_in[6];
    const float* b2    = (const float*)d_in[7];
    const float* l1W   = (const float*)d_in[8];
    const float* l1b   = (const float*)d_in[9];
    const float* axW   = (const float*)d_in[10];
    const float* axb   = (const float*)d_in[11];
    const float* l2W   = (const float*)d_in[12];
    const float* l2b   = (const float*)d_in[13];
    float* out = (float*)d_out;

    const int TB = 256;
    k_reset  <<<(NN + TB - 1) / TB, TB>>>();
    k_detect <<<(262144 + TB - 1) / TB, TB>>>((const int*)ei, (const int*)batch);
    k_convert<<<(NE + TB - 1) / TB, TB>>>(ei, batch);
    k_scan   <<<1, 1024>>>();
    k_scatter<<<(NE + TB - 1) / TB, TB>>>();

    k_sgemm<-1, 0><<<(NN + 127) / 128, 256>>>(x, W1, NN);        // x @ W1 -> bufA
    k_spmm <0, 1> <<<(NN * 32 + TB - 1) / TB, TB>>>(b1);         // aggregate -> bufB
    k_sgemm<1, 0><<<(NN + 127) / 128, 256>>>(nullptr, W2, NN);   // bufB @ W2 -> bufA
    k_spmm <0, 1> <<<(NN * 32 + TB - 1) / TB, TB>>>(b2);         // aggregate -> bufB

    k_bounds<<<(NN + TB - 1) / TB, TB>>>();
    k_head<1><<<NG, 128>>>(ax, l1W, l1b, axW, axb, l2W, l2b, out);
}

// round 12
// speedup vs baseline: 1.1879x; 1.1354x over previous
#include <cuda_runtime.h>
#include <cuda_bf16.h>
#include <math.h>

#define NN 50000
#define NE 640000
#define F  128
#define NG 512

#define SC   256
#define NBLK ((NN + SC - 1) / SC)   // 196

typedef unsigned long long ull;

// ---------------- scratch (device globals, no allocation) ----------------
__device__ int   g_ei32flag;
__device__ int   g_b32flag;
__device__ int   g_src[NE];
__device__ int   g_dst[NE];
__device__ int   g_batch[NN];
__device__ int   g_degE[NN];
__device__ int   g_cursor[NN];
__device__ int   g_rowoff[NN + 1];
__device__ int   g_bsum[NBLK];
__device__ int   g_boff[NBLK];
__device__ int   g_col[NE];
__device__ float g_nrm[NE];            // dinv[src] per CSR slot
__device__ float g_dinv[NN];
__device__ __align__(16) float g_bufA[NN * F];
__device__ __align__(16) float g_bufB[NN * F];
__device__ int   g_gstart[NG + 1];

template <int B> __device__ __forceinline__ float* bufptr() {
    return (B == 0) ? g_bufA : g_bufB;
}

// packed fp32x2 helpers (Blackwell FFMA2 via PTX)
__device__ __forceinline__ void ffma2(ull& acc, ull a, ull b) {
    asm("fma.rn.f32x2 %0, %1, %2, %0;" : "+l"(acc) : "l"(a), "l"(b));
}
__device__ __forceinline__ ull pack2(float x) {
    ull r;
    asm("mov.b64 %0, {%1, %1};" : "=l"(r) : "r"(__float_as_uint(x)));
    return r;
}

// ---------------- dtype detection + normalization ----------------
__global__ void k_reset() {
    int i = blockIdx.x * blockDim.x + threadIdx.x;
    if (i == 0) { g_ei32flag = 0; g_b32flag = 0; }
    if (i < NN) { g_degE[i] = 0; g_cursor[i] = 0; }
}

__global__ void k_detect(const int* __restrict__ ei_raw,
                         const int* __restrict__ batch_raw) {
    int i = blockIdx.x * blockDim.x + threadIdx.x;
    int v = 0;
    for (int j = 2 * i + 1; j < 2 * NE; j += 2 * 262144) v |= ei_raw[j];
    if (v) atomicOr(&g_ei32flag, 1);
    int bsum = 0;
    for (int j = 2 * i + 1; j < NN; j += 2 * 262144) bsum |= batch_raw[j];
    if (bsum) atomicOr(&g_b32flag, 1);
}

// convert + degree count fused
__global__ void k_convert(const void* __restrict__ ei_raw,
                          const void* __restrict__ batch_raw) {
    int i = blockIdx.x * blockDim.x + threadIdx.x;
    if (i < NE) {
        int s, d;
        if (g_ei32flag) {
            const int* p = (const int*)ei_raw;
            s = p[i]; d = p[NE + i];
        } else {
            const long long* p = (const long long*)ei_raw;
            s = (int)p[i]; d = (int)p[NE + i];
        }
        s = min(max(s, 0), NN - 1);
        d = min(max(d, 0), NN - 1);
        g_src[i] = s;
        g_dst[i] = d;
        atomicAdd(&g_degE[d], 1);
    }
    if (i < NN) {
        int b;
        if (g_b32flag) b = ((const int*)batch_raw)[i];
        else           b = (int)((const long long*)batch_raw)[i];
        g_batch[i] = min(max(b, 0), NG - 1);
    }
}

// ---------------- parallel 3-phase exclusive scan of g_degE ----------------
// Phase 1: per-256-chunk sums (+ fused dinv)
__global__ __launch_bounds__(SC) void k_partsum() {
    __shared__ int ws[SC / 32];
    int b = blockIdx.x, t = threadIdx.x;
    int lane = t & 31, w = t >> 5;
    int i = b * SC + t;
    int v = (i < NN) ? g_degE[i] : 0;
    if (i < NN) g_dinv[i] = rsqrtf((float)(v + 1));  // +1 self loop
    int x = v;
    #pragma unroll
    for (int o = 16; o > 0; o >>= 1) x += __shfl_down_sync(0xffffffffu, x, o);
    if (lane == 0) ws[w] = x;
    __syncthreads();
    if (t == 0) {
        int s = 0;
        #pragma unroll
        for (int k = 0; k < SC / 32; k++) s += ws[k];
        g_bsum[b] = s;
    }
}

// Phase 2: exclusive scan of NBLK (<=256) chunk sums in one block
__global__ __launch_bounds__(256) void k_bscan() {
    __shared__ int wincl[8];
    int t = threadIdx.x, lane = t & 31, w = t >> 5;
    int v = (t < NBLK) ? g_bsum[t] : 0;
    int x = v;
    #pragma unroll
    for (int o = 1; o < 32; o <<= 1) {
        int y = __shfl_up_sync(0xffffffffu, x, o);
        if (lane >= o) x += y;
    }
    if (lane == 31) wincl[w] = x;
    __syncthreads();
    int woff = 0;
    #pragma unroll
    for (int k = 0; k < 8; k++) woff += (k < w) ? wincl[k] : 0;
    int excl = woff + x - v;
    if (t < NBLK) g_boff[t] = excl;
    if (t == NBLK - 1) g_rowoff[NN] = excl + v;   // total
}

// Phase 3: per-chunk local exclusive scan + chunk offset
__global__ __launch_bounds__(SC) void k_apply() {
    __shared__ int wincl[SC / 32];
    int b = blockIdx.x, t = threadIdx.x;
    int lane = t & 31, w = t >> 5;
    int i = b * SC + t;
    int v = (i < NN) ? g_degE[i] : 0;
    int x = v;
    #pragma unroll
    for (int o = 1; o < 32; o <<= 1) {
        int y = __shfl_up_sync(0xffffffffu, x, o);
        if (lane >= o) x += y;
    }
    if (lane == 31) wincl[w] = x;
    __syncthreads();
    int woff = 0;
    #pragma unroll
    for (int k = 0; k < SC / 32; k++) woff += (k < w) ? wincl[k] : 0;
    if (i < NN) g_rowoff[i] = g_boff[b] + woff + x - v;
}

// scatter + per-edge norm fused
__global__ void k_scatter() {
    int e = blockIdx.x * blockDim.x + threadIdx.x;
    if (e < NE) {
        int s = g_src[e];
        int d = g_dst[e];
        int pos = atomicAdd(&g_cursor[d], 1);
        int idx = g_rowoff[d] + pos;
        g_col[idx] = s;
        g_nrm[idx] = g_dinv[s];
    }
}

// ---------------- dense GEMM: C[M,128] = A[M,128] @ W[128,128] (f32x2 FFMA2) ----------------
template <int SRC, int DST>
__global__ __launch_bounds__(256) void k_sgemm(const float* __restrict__ X,
                                               const float* __restrict__ W, int M) {
    const float* A = (SRC < 0) ? X : bufptr<SRC>();
    float* C = bufptr<DST>();
    __shared__ float As[16][128];
    __shared__ float Bs[16][128];
    int row0 = blockIdx.x * 128;
    int tid = threadIdx.x;
    int tr = (tid >> 4) << 3;
    int tc = (tid & 15) << 3;
    ull acc2[8][4];
    #pragma unroll
    for (int i = 0; i < 8; i++)
        #pragma unroll
        for (int j = 0; j < 4; j++) acc2[i][j] = 0ull;

    for (int k0 = 0; k0 < 128; k0 += 16) {
        #pragma unroll
        for (int it = 0; it < 2; it++) {   // A tile 128x16 (transposed into As[k][row])
            int idx = tid + it * 256;
            int r = idx >> 2;
            int c4 = (idx & 3) << 2;
            float4 a = (row0 + r < M)
                ? *(const float4*)(A + (size_t)(row0 + r) * 128 + k0 + c4)
                : make_float4(0.f, 0.f, 0.f, 0.f);
            As[c4 + 0][r] = a.x; As[c4 + 1][r] = a.y;
            As[c4 + 2][r] = a.z; As[c4 + 3][r] = a.w;
        }
        #pragma unroll
        for (int it = 0; it < 2; it++) {   // W tile 16x128
            int idx = tid + it * 256;
            int r = idx >> 5;
            int c4 = (idx & 31) << 2;
            *(float4*)&Bs[r][c4] = *(const float4*)(W + (k0 + r) * 128 + c4);
        }
        __syncthreads();
        #pragma unroll
        for (int k = 0; k < 16; k++) {
            ull ra2[8], rb2[4];
            #pragma unroll
            for (int i = 0; i < 8; i++) ra2[i] = pack2(As[k][tr + i]);
            #pragma unroll
            for (int j = 0; j < 4; j++)
                rb2[j] = *reinterpret_cast<const ull*>(&Bs[k][tc + 2 * j]);
            #pragma unroll
            for (int i = 0; i < 8; i++)
                #pragma unroll
                for (int j = 0; j < 4; j++) ffma2(acc2[i][j], ra2[i], rb2[j]);
        }
        __syncthreads();
    }
    #pragma unroll
    for (int i = 0; i < 8; i++) {
        int r = row0 + tr + i;
        if (r < M) {
            float2 p0 = *reinterpret_cast<float2*>(&acc2[i][0]);
            float2 p1 = *reinterpret_cast<float2*>(&acc2[i][1]);
            float2 p2 = *reinterpret_cast<float2*>(&acc2[i][2]);
            float2 p3 = *reinterpret_cast<float2*>(&acc2[i][3]);
            *(float4*)(C + (size_t)r * 128 + tc)     = make_float4(p0.x, p0.y, p1.x, p1.y);
            *(float4*)(C + (size_t)r * 128 + tc + 4) = make_float4(p2.x, p2.y, p3.x, p3.y);
        }
    }
}

// ---------------- SpMM aggregate + bias + relu (warp per node, no shuffles) ----------------
template <int SRC, int DST>
__global__ void k_spmm(const float* __restrict__ bias) {
    const float* H = bufptr<SRC>();
    float* O = bufptr<DST>();
    int v = (blockIdx.x * blockDim.x + threadIdx.x) >> 5;
    int lane = threadIdx.x & 31;
    if (v >= NN) return;
    float dv = g_dinv[v];
    float4 h = *(const float4*)(H + (size_t)v * 128 + lane * 4);
    float4 acc = make_float4(dv * h.x, dv * h.y, dv * h.z, dv * h.w);  // self loop
    int beg = g_rowoff[v], end = g_rowoff[v + 1];
    int j = beg;
    for (; j + 4 <= end; j += 4) {
        int s0 = g_col[j], s1 = g_col[j + 1], s2 = g_col[j + 2], s3 = g_col[j + 3];
        float d0 = g_nrm[j], d1 = g_nrm[j + 1], d2 = g_nrm[j + 2], d3 = g_nrm[j + 3];
        float4 h0 = *(const float4*)(H + (size_t)s0 * 128 + lane * 4);
        float4 h1 = *(const float4*)(H + (size_t)s1 * 128 + lane * 4);
        float4 h2 = *(const float4*)(H + (size_t)s2 * 128 + lane * 4);
        float4 h3 = *(const float4*)(H + (size_t)s3 * 128 + lane * 4);
        acc.x = fmaf(d0, h0.x, acc.x); acc.y = fmaf(d0, h0.y, acc.y);
        acc.z = fmaf(d0, h0.z, acc.z); acc.w = fmaf(d0, h0.w, acc.w);
        acc.x = fmaf(d1, h1.x, acc.x); acc.y = fmaf(d1, h1.y, acc.y);
        acc.z = fmaf(d1, h1.z, acc.z); acc.w = fmaf(d1, h1.w, acc.w);
        acc.x = fmaf(d2, h2.x, acc.x); acc.y = fmaf(d2, h2.y, acc.y);
        acc.z = fmaf(d2, h2.z, acc.z); acc.w = fmaf(d2, h2.w, acc.w);
        acc.x = fmaf(d3, h3.x, acc.x); acc.y = fmaf(d3, h3.y, acc.y);
        acc.z = fmaf(d3, h3.z, acc.z); acc.w = fmaf(d3, h3.w, acc.w);
    }
    for (; j < end; j++) {
        int s = g_col[j];
        float ds = g_nrm[j];
        float4 hs = *(const float4*)(H + (size_t)s * 128 + lane * 4);
        acc.x = fmaf(ds, hs.x, acc.x); acc.y = fmaf(ds, hs.y, acc.y);
        acc.z = fmaf(ds, hs.z, acc.z); acc.w = fmaf(ds, hs.w, acc.w);
    }
    float4 b = *(const float4*)(bias + lane * 4);
    float4 o;
    o.x = fmaxf(fmaf(dv, acc.x, b.x), 0.f);
    o.y = fmaxf(fmaf(dv, acc.y, b.y), 0.f);
    o.z = fmaxf(fmaf(dv, acc.z, b.z), 0.f);
    o.w = fmaxf(fmaf(dv, acc.w, b.w), 0.f);
    *(float4*)(O + (size_t)v * 128 + lane * 4) = o;
}

// ---------------- graph segment boundaries (batch is sorted) ----------------
__global__ void k_bounds() {
    int i = blockIdx.x * blockDim.x + threadIdx.x;
    if (i >= NN) return;
    int b = g_batch[i];
    if (i == 0) {
        for (int g = 0; g <= b; g++) g_gstart[g] = 0;
    } else {
        int bp = g_batch[i - 1];
        for (int g = bp + 1; g <= b; g++) g_gstart[g] = i;
    }
    if (i == NN - 1) {
        for (int g = b + 1; g <= NG; g++) g_gstart[g] = NN;
    }
}

// ---------------- mean pool + MLP head (block per graph) ----------------
template <int SRC>
__global__ __launch_bounds__(128) void k_head(
    const float* __restrict__ ax,
    const float* __restrict__ l1W, const float* __restrict__ l1b,
    const float* __restrict__ axW, const float* __restrict__ axb,
    const float* __restrict__ l2W, const float* __restrict__ l2b,
    float* __restrict__ out) {
    const float* H = bufptr<SRC>();
    int g = blockIdx.x, t = threadIdx.x;
    __shared__ float pooled[128];
    __shared__ float axs[64];
    __shared__ float z[192];
    int s = g_gstart[g], e = g_gstart[g + 1];
    float acc = 0.f;
    for (int v = s; v < e; v++) acc += H[(size_t)v * 128 + t];
    pooled[t] = acc / (float)max(e - s, 1);
    if (t < 64) axs[t] = ax[g * 64 + t];
    __syncthreads();
    float go = l1b[t];
    #pragma unroll 8
    for (int k = 0; k < 128; k++) go = fmaf(pooled[k], l1W[k * 128 + t], go);
    z[t] = go;
    if (t < 64) {
        float ao = axb[t];
        #pragma unroll 8
        for (int k = 0; k < 64; k++) ao = fmaf(axs[k], axW[k * 64 + t], ao);
        z[128 + t] = ao;
    }
    __syncthreads();
    if (t < 8) {
        float o = l2b[t];
        #pragma unroll 8
        for (int k = 0; k < 192; k++) o = fmaf(z[k], l2W[k * 8 + t], o);
        out[g * 8 + t] = o;
    }
}

// ---------------- launch ----------------
extern "C" void kernel_launch(void* const* d_in, const int* in_sizes, int n_in,
                              void* d_out, int out_size) {
    const float* x     = (const float*)d_in[0];
    const void*  ei    = d_in[1];
    const void*  batch = d_in[2];
    const float* ax    = (const float*)d_in[3];
    const float* W1    = (const float*)d_in[4];
    const float* b1    = (const float*)d_in[5];
    const float* W2    = (const float*)d_in[6];
    const float* b2    = (const float*)d_in[7];
    const float* l1W   = (const float*)d_in[8];
    const float* l1b   = (const float*)d_in[9];
    const float* axW   = (const float*)d_in[10];
    const float* axb   = (const float*)d_in[11];
    const float* l2W   = (const float*)d_in[12];
    const float* l2b   = (const float*)d_in[13];
    float* out = (float*)d_out;

    const int TB = 256;
    k_reset  <<<(NN + TB - 1) / TB, TB>>>();
    k_detect <<<(262144 + TB - 1) / TB, TB>>>((const int*)ei, (const int*)batch);
    k_convert<<<(NE + TB - 1) / TB, TB>>>(ei, batch);
    k_partsum<<<NBLK, SC>>>();
    k_bscan  <<<1, 256>>>();
    k_apply  <<<NBLK, SC>>>();
    k_scatter<<<(NE + TB - 1) / TB, TB>>>();

    k_sgemm<-1, 0><<<(NN + 127) / 128, 256>>>(x, W1, NN);        // x @ W1 -> bufA
    k_spmm <0, 1> <<<(NN * 32 + TB - 1) / TB, TB>>>(b1);         // aggregate -> bufB
    k_sgemm<1, 0><<<(NN + 127) / 128, 256>>>(nullptr, W2, NN);   // bufB @ W2 -> bufA
    k_spmm <0, 1> <<<(NN * 32 + TB - 1) / TB, TB>>>(b2);         // aggregate -> bufB

    k_bounds<<<(NN + TB - 1) / TB, TB>>>();
    k_head<1><<<NG, 128>>>(ax, l1W, l1b, axW, axb, l2W, l2b, out);
}

// round 14
// speedup vs baseline: 1.2621x; 1.0625x over previous
#include <cuda_runtime.h>
#include <cuda_bf16.h>
#include <math.h>

#define NN 50000
#define NE 640000
#define F  128
#define NG 512

#define SC   256
#define NBLK ((NN + SC - 1) / SC)   // 196

typedef unsigned long long ull;

// ---------------- scratch (device globals, no allocation) ----------------
__device__ int   g_ei32flag;
__device__ int   g_b32flag;
__device__ int   g_src[NE];
__device__ int   g_dst[NE];
__device__ int   g_batch[NN];
__device__ int   g_degE[NN];
__device__ int   g_cursor[NN];
__device__ int   g_rowoff[NN + 1];
__device__ int   g_bsum[NBLK];
__device__ int   g_boff[NBLK];
__device__ int   g_col[NE];
__device__ float g_nrm[NE];            // dinv[src] per CSR slot
__device__ float g_dinv[NN];
__device__ __align__(16) float g_bufA[NN * F];
__device__ __align__(16) float g_bufB[NN * F];
__device__ int   g_gstart[NG + 1];

template <int B> __device__ __forceinline__ float* bufptr() {
    return (B == 0) ? g_bufA : g_bufB;
}

// packed fp32x2 helpers (Blackwell FFMA2 via PTX)
__device__ __forceinline__ void ffma2(ull& acc, ull a, ull b) {
    asm("fma.rn.f32x2 %0, %1, %2, %0;" : "+l"(acc) : "l"(a), "l"(b));
}
__device__ __forceinline__ ull pack2(float x) {
    ull r;
    asm("mov.b64 %0, {%1, %1};" : "=l"(r) : "r"(__float_as_uint(x)));
    return r;
}

// ---------------- dtype detection + normalization ----------------
__global__ void k_reset() {
    int i = blockIdx.x * blockDim.x + threadIdx.x;
    if (i == 0) { g_ei32flag = 0; g_b32flag = 0; }
    if (i < NN) { g_degE[i] = 0; g_cursor[i] = 0; }
}

__global__ void k_detect(const int* __restrict__ ei_raw,
                         const int* __restrict__ batch_raw) {
    int i = blockIdx.x * blockDim.x + threadIdx.x;
    int v = 0;
    for (int j = 2 * i + 1; j < 2 * NE; j += 2 * 262144) v |= ei_raw[j];
    if (v) atomicOr(&g_ei32flag, 1);
    int bsum = 0;
    for (int j = 2 * i + 1; j < NN; j += 2 * 262144) bsum |= batch_raw[j];
    if (bsum) atomicOr(&g_b32flag, 1);
}

// convert + degree count fused
__global__ void k_convert(const void* __restrict__ ei_raw,
                          const void* __restrict__ batch_raw) {
    int i = blockIdx.x * blockDim.x + threadIdx.x;
    if (i < NE) {
        int s, d;
        if (g_ei32flag) {
            const int* p = (const int*)ei_raw;
            s = p[i]; d = p[NE + i];
        } else {
            const long long* p = (const long long*)ei_raw;
            s = (int)p[i]; d = (int)p[NE + i];
        }
        s = min(max(s, 0), NN - 1);
        d = min(max(d, 0), NN - 1);
        g_src[i] = s;
        g_dst[i] = d;
        atomicAdd(&g_degE[d], 1);
    }
    if (i < NN) {
        int b;
        if (g_b32flag) b = ((const int*)batch_raw)[i];
        else           b = (int)((const long long*)batch_raw)[i];
        g_batch[i] = min(max(b, 0), NG - 1);
    }
}

// ---------------- parallel 3-phase exclusive scan of g_degE ----------------
__global__ __launch_bounds__(SC) void k_partsum() {
    __shared__ int ws[SC / 32];
    int b = blockIdx.x, t = threadIdx.x;
    int lane = t & 31, w = t >> 5;
    int i = b * SC + t;
    int v = (i < NN) ? g_degE[i] : 0;
    if (i < NN) g_dinv[i] = rsqrtf((float)(v + 1));  // +1 self loop
    int x = v;
    #pragma unroll
    for (int o = 16; o > 0; o >>= 1) x += __shfl_down_sync(0xffffffffu, x, o);
    if (lane == 0) ws[w] = x;
    __syncthreads();
    if (t == 0) {
        int s = 0;
        #pragma unroll
        for (int k = 0; k < SC / 32; k++) s += ws[k];
        g_bsum[b] = s;
    }
}

__global__ __launch_bounds__(256) void k_bscan() {
    __shared__ int wincl[8];
    int t = threadIdx.x, lane = t & 31, w = t >> 5;
    int v = (t < NBLK) ? g_bsum[t] : 0;
    int x = v;
    #pragma unroll
    for (int o = 1; o < 32; o <<= 1) {
        int y = __shfl_up_sync(0xffffffffu, x, o);
        if (lane >= o) x += y;
    }
    if (lane == 31) wincl[w] = x;
    __syncthreads();
    int woff = 0;
    #pragma unroll
    for (int k = 0; k < 8; k++) woff += (k < w) ? wincl[k] : 0;
    int excl = woff + x - v;
    if (t < NBLK) g_boff[t] = excl;
    if (t == NBLK - 1) g_rowoff[NN] = excl + v;   // total
}

__global__ __launch_bounds__(SC) void k_apply() {
    __shared__ int wincl[SC / 32];
    int b = blockIdx.x, t = threadIdx.x;
    int lane = t & 31, w = t >> 5;
    int i = b * SC + t;
    int v = (i < NN) ? g_degE[i] : 0;
    int x = v;
    #pragma unroll
    for (int o = 1; o < 32; o <<= 1) {
        int y = __shfl_up_sync(0xffffffffu, x, o);
        if (lane >= o) x += y;
    }
    if (lane == 31) wincl[w] = x;
    __syncthreads();
    int woff = 0;
    #pragma unroll
    for (int k = 0; k < SC / 32; k++) woff += (k < w) ? wincl[k] : 0;
    if (i < NN) g_rowoff[i] = g_boff[b] + woff + x - v;
}

// scatter + per-edge norm fused
__global__ void k_scatter() {
    int e = blockIdx.x * blockDim.x + threadIdx.x;
    if (e < NE) {
        int s = g_src[e];
        int d = g_dst[e];
        int pos = atomicAdd(&g_cursor[d], 1);
        int idx = g_rowoff[d] + pos;
        g_col[idx] = s;
        g_nrm[idx] = g_dinv[s];
    }
}

// ---------------- dense GEMM: C[M,128] = A[M,128] @ W[128,128] (f32x2 FFMA2) ----------------
template <int SRC, int DST>
__global__ __launch_bounds__(256) void k_sgemm(const float* __restrict__ X,
                                               const float* __restrict__ W, int M) {
    const float* A = (SRC < 0) ? X : bufptr<SRC>();
    float* C = bufptr<DST>();
    __shared__ float As[16][128];
    __shared__ float Bs[16][128];
    int row0 = blockIdx.x * 128;
    int tid = threadIdx.x;
    int tr = (tid >> 4) << 3;
    int tc = (tid & 15) << 3;
    ull acc2[8][4];
    #pragma unroll
    for (int i = 0; i < 8; i++)
        #pragma unroll
        for (int j = 0; j < 4; j++) acc2[i][j] = 0ull;

    for (int k0 = 0; k0 < 128; k0 += 16) {
        #pragma unroll
        for (int it = 0; it < 2; it++) {   // A tile 128x16 (transposed into As[k][row])
            int idx = tid + it * 256;
            int r = idx >> 2;
            int c4 = (idx & 3) << 2;
            float4 a = (row0 + r < M)
                ? *(const float4*)(A + (size_t)(row0 + r) * 128 + k0 + c4)
                : make_float4(0.f, 0.f, 0.f, 0.f);
            As[c4 + 0][r] = a.x; As[c4 + 1][r] = a.y;
            As[c4 + 2][r] = a.z; As[c4 + 3][r] = a.w;
        }
        #pragma unroll
        for (int it = 0; it < 2; it++) {   // W tile 16x128
            int idx = tid + it * 256;
            int r = idx >> 5;
            int c4 = (idx & 31) << 2;
            *(float4*)&Bs[r][c4] = *(const float4*)(W + (k0 + r) * 128 + c4);
        }
        __syncthreads();
        #pragma unroll
        for (int k = 0; k < 16; k++) {
            ull ra2[8], rb2[4];
            #pragma unroll
            for (int i = 0; i < 8; i++) ra2[i] = pack2(As[k][tr + i]);
            #pragma unroll
            for (int j = 0; j < 4; j++)
                rb2[j] = *reinterpret_cast<const ull*>(&Bs[k][tc + 2 * j]);
            #pragma unroll
            for (int i = 0; i < 8; i++)
                #pragma unroll
                for (int j = 0; j < 4; j++) ffma2(acc2[i][j], ra2[i], rb2[j]);
        }
        __syncthreads();
    }
    #pragma unroll
    for (int i = 0; i < 8; i++) {
        int r = row0 + tr + i;
        if (r < M) {
            float2 p0 = *reinterpret_cast<float2*>(&acc2[i][0]);
            float2 p1 = *reinterpret_cast<float2*>(&acc2[i][1]);
            float2 p2 = *reinterpret_cast<float2*>(&acc2[i][2]);
            float2 p3 = *reinterpret_cast<float2*>(&acc2[i][3]);
            *(float4*)(C + (size_t)r * 128 + tc)     = make_float4(p0.x, p0.y, p1.x, p1.y);
            *(float4*)(C + (size_t)r * 128 + tc + 4) = make_float4(p2.x, p2.y, p3.x, p3.y);
        }
    }
}

// ---------------- SpMM aggregate + bias + relu (warp per node, no shuffles) ----------------
template <int SRC, int DST>
__global__ void k_spmm(const float* __restrict__ bias) {
    const float* H = bufptr<SRC>();
    float* O = bufptr<DST>();
    int v = (blockIdx.x * blockDim.x + threadIdx.x) >> 5;
    int lane = threadIdx.x & 31;
    if (v >= NN) return;
    float dv = g_dinv[v];
    float4 h = *(const float4*)(H + (size_t)v * 128 + lane * 4);
    float4 acc = make_float4(dv * h.x, dv * h.y, dv * h.z, dv * h.w);  // self loop
    int beg = g_rowoff[v], end = g_rowoff[v + 1];
    int j = beg;
    for (; j + 4 <= end; j += 4) {
        int s0 = g_col[j], s1 = g_col[j + 1], s2 = g_col[j + 2], s3 = g_col[j + 3];
        float d0 = g_nrm[j], d1 = g_nrm[j + 1], d2 = g_nrm[j + 2], d3 = g_nrm[j + 3];
        float4 h0 = *(const float4*)(H + (size_t)s0 * 128 + lane * 4);
        float4 h1 = *(const float4*)(H + (size_t)s1 * 128 + lane * 4);
        float4 h2 = *(const float4*)(H + (size_t)s2 * 128 + lane * 4);
        float4 h3 = *(const float4*)(H + (size_t)s3 * 128 + lane * 4);
        acc.x = fmaf(d0, h0.x, acc.x); acc.y = fmaf(d0, h0.y, acc.y);
        acc.z = fmaf(d0, h0.z, acc.z); acc.w = fmaf(d0, h0.w, acc.w);
        acc.x = fmaf(d1, h1.x, acc.x); acc.y = fmaf(d1, h1.y, acc.y);
        acc.z = fmaf(d1, h1.z, acc.z); acc.w = fmaf(d1, h1.w, acc.w);
        acc.x = fmaf(d2, h2.x, acc.x); acc.y = fmaf(d2, h2.y, acc.y);
        acc.z = fmaf(d2, h2.z, acc.z); acc.w = fmaf(d2, h2.w, acc.w);
        acc.x = fmaf(d3, h3.x, acc.x); acc.y = fmaf(d3, h3.y, acc.y);
        acc.z = fmaf(d3, h3.z, acc.z); acc.w = fmaf(d3, h3.w, acc.w);
    }
    for (; j < end; j++) {
        int s = g_col[j];
        float ds = g_nrm[j];
        float4 hs = *(const float4*)(H + (size_t)s * 128 + lane * 4);
        acc.x = fmaf(ds, hs.x, acc.x); acc.y = fmaf(ds, hs.y, acc.y);
        acc.z = fmaf(ds, hs.z, acc.z); acc.w = fmaf(ds, hs.w, acc.w);
    }
    float4 b = *(const float4*)(bias + lane * 4);
    float4 o;
    o.x = fmaxf(fmaf(dv, acc.x, b.x), 0.f);
    o.y = fmaxf(fmaf(dv, acc.y, b.y), 0.f);
    o.z = fmaxf(fmaf(dv, acc.z, b.z), 0.f);
    o.w = fmaxf(fmaf(dv, acc.w, b.w), 0.f);
    *(float4*)(O + (size_t)v * 128 + lane * 4) = o;
}

// ---------------- graph segment boundaries (batch is sorted) ----------------
__global__ void k_bounds() {
    int i = blockIdx.x * blockDim.x + threadIdx.x;
    if (i >= NN) return;
    int b = g_batch[i];
    if (i == 0) {
        for (int g = 0; g <= b; g++) g_gstart[g] = 0;
    } else {
        int bp = g_batch[i - 1];
        for (int g = bp + 1; g <= b; g++) g_gstart[g] = i;
    }
    if (i == NN - 1) {
        for (int g = b + 1; g <= NG; g++) g_gstart[g] = NN;
    }
}

// ---------------- mean pool + MLP head (block per graph) ----------------
template <int SRC>
__global__ __launch_bounds__(128) void k_head(
    const float* __restrict__ ax,
    const float* __restrict__ l1W, const float* __restrict__ l1b,
    const float* __restrict__ axW, const float* __restrict__ axb,
    const float* __restrict__ l2W, const float* __restrict__ l2b,
    float* __restrict__ out) {
    const float* H = bufptr<SRC>();
    int g = blockIdx.x, t = threadIdx.x;
    __shared__ float pooled[128];
    __shared__ float axs[64];
    __shared__ float z[192];
    int s = g_gstart[g], e = g_gstart[g + 1];
    float acc = 0.f;
    for (int v = s; v < e; v++) acc += H[(size_t)v * 128 + t];
    pooled[t] = acc / (float)max(e - s, 1);
    if (t < 64) axs[t] = ax[g * 64 + t];
    __syncthreads();
    float go = l1b[t];
    #pragma unroll 8
    for (int k = 0; k < 128; k++) go = fmaf(pooled[k], l1W[k * 128 + t], go);
    z[t] = go;
    if (t < 64) {
        float ao = axb[t];
        #pragma unroll 8
        for (int k = 0; k < 64; k++) ao = fmaf(axs[k], axW[k * 64 + t], ao);
        z[128 + t] = ao;
    }
    __syncthreads();
    if (t < 8) {
        float o = l2b[t];
        #pragma unroll 8
        for (int k = 0; k < 192; k++) o = fmaf(z[k], l2W[k * 8 + t], o);
        out[g * 8 + t] = o;
    }
}

// ---------------- launch (fork/join: GEMM1 overlaps CSR build) ----------------
extern "C" void kernel_launch(void* const* d_in, const int* in_sizes, int n_in,
                              void* d_out, int out_size) {
    const float* x     = (const float*)d_in[0];
    const void*  ei    = d_in[1];
    const void*  batch = d_in[2];
    const float* ax    = (const float*)d_in[3];
    const float* W1    = (const float*)d_in[4];
    const float* b1    = (const float*)d_in[5];
    const float* W2    = (const float*)d_in[6];
    const float* b2    = (const float*)d_in[7];
    const float* l1W   = (const float*)d_in[8];
    const float* l1b   = (const float*)d_in[9];
    const float* axW   = (const float*)d_in[10];
    const float* axb   = (const float*)d_in[11];
    const float* l2W   = (const float*)d_in[12];
    const float* l2b   = (const float*)d_in[13];
    float* out = (float*)d_out;

    // side stream + events created once on the first (uncaptured) call;
    // during graph capture they already exist, so only launches/events are captured.
    static cudaStream_t s2 = nullptr;
    static cudaEvent_t evFork = nullptr, evJoin = nullptr;
    if (!s2) {
        cudaStreamCreateWithFlags(&s2, cudaStreamNonBlocking);
        cudaEventCreateWithFlags(&evFork, cudaEventDisableTiming);
        cudaEventCreateWithFlags(&evJoin, cudaEventDisableTiming);
    }

    const int TB = 256;

    // fork: GEMM1 (independent of CSR) on side stream
    cudaEventRecord(evFork, 0);
    cudaStreamWaitEvent(s2, evFork, 0);
    k_sgemm<-1, 0><<<(NN + 127) / 128, 256, 0, s2>>>(x, W1, NN);   // x @ W1 -> bufA
    cudaEventRecord(evJoin, s2);

    // CSR build chain on capture (default) stream
    k_reset  <<<(NN + TB - 1) / TB, TB>>>();
    k_detect <<<(262144 + TB - 1) / TB, TB>>>((const int*)ei, (const int*)batch);
    k_convert<<<(NE + TB - 1) / TB, TB>>>(ei, batch);
    k_partsum<<<NBLK, SC>>>();
    k_bscan  <<<1, 256>>>();
    k_apply  <<<NBLK, SC>>>();
    k_scatter<<<(NE + TB - 1) / TB, TB>>>();
    k_bounds <<<(NN + TB - 1) / TB, TB>>>();

    // join: SpMM needs both CSR (default stream) and bufA (s2)
    cudaStreamWaitEvent(0, evJoin, 0);

    k_spmm <0, 1> <<<(NN * 32 + TB - 1) / TB, TB>>>(b1);           // aggregate -> bufB
    k_sgemm<1, 0> <<<(NN + 127) / 128, 256>>>(nullptr, W2, NN);    // bufB @ W2 -> bufA
    k_spmm <0, 1> <<<(NN * 32 + TB - 1) / TB, TB>>>(b2);           // aggregate -> bufB

    k_head<1><<<NG, 128>>>(ax, l1W, l1b, axW, axb, l2W, l2b, out);
}